// round 4
// baseline (speedup 1.0000x reference)
#include <cuda_runtime.h>
#include <cstdint>

#define B_ROWS 8192
#define K_DIM  784
#define N_DIM  800
#define NSTEPS 25

// ---------------- device scratch (static globals: no runtime allocation) ----
__device__ float g_sp  [B_ROWS * K_DIM];   // Poisson spike matrix {0, 0.5, 1}
__device__ float g_mem1[B_ROWS * N_DIM];   // membrane potential
__device__ float g_S   [B_ROWS * N_DIM];   // spike counts (sum over t of out_t)
__device__ uint2 g_keys[NSTEPS];           // per-step threefry keys

// ---------------- threefry2x32 (matches JAX, 20 rounds) --------------------
__device__ __forceinline__ void threefry2x32(uint32_t k0, uint32_t k1,
                                             uint32_t x0, uint32_t x1,
                                             uint32_t &o0, uint32_t &o1) {
    uint32_t ks0 = k0, ks1 = k1, ks2 = 0x1BD11BDAu ^ k0 ^ k1;
    x0 += ks0; x1 += ks1;
#define TF_R(r) { x0 += x1; x1 = __funnelshift_l(x1, x1, (r)); x1 ^= x0; }
    TF_R(13) TF_R(15) TF_R(26) TF_R(6)
    x0 += ks1; x1 += ks2 + 1u;
    TF_R(17) TF_R(29) TF_R(16) TF_R(24)
    x0 += ks2; x1 += ks0 + 2u;
    TF_R(13) TF_R(15) TF_R(26) TF_R(6)
    x0 += ks0; x1 += ks1 + 3u;
    TF_R(17) TF_R(29) TF_R(16) TF_R(24)
    x0 += ks1; x1 += ks2 + 4u;
    TF_R(13) TF_R(15) TF_R(26) TF_R(6)
    x0 += ks2; x1 += ks0 + 5u;
#undef TF_R
    o0 = x0; o1 = x1;
}

// ---------------- init: per-step keys (partitionable split of key(42)) ------
__global__ void k_init() {
    int t = threadIdx.x;
    if (t < NSTEPS) {
        uint32_t o0, o1;
        threefry2x32(0u, 42u, 0u, (uint32_t)t, o0, o1);
        g_keys[t] = make_uint2(o0, o1);
    }
}

// ---------------- zero state ------------------------------------------------
__global__ void k_zero() {
    int i = blockIdx.x * blockDim.x + threadIdx.x;
    if (i < B_ROWS * N_DIM) { g_mem1[i] = 0.0f; g_S[i] = 0.0f; }
}

// ---------------- per-step spike (Poisson) generation -----------------------
// r = uniform(key_t)[i]; temp = (2r <= |x|) * sign(x); sp = 0.5*(temp+1)
// sp in {0, 0.5, 1} — every GEMM product sp*w is EXACT in fp32.
__global__ void k_spike(const float* __restrict__ inp, int t) {
    int i = blockIdx.x * blockDim.x + threadIdx.x;
    if (i >= B_ROWS * K_DIM) return;
    uint2 key = g_keys[t];
    uint32_t o0, o1;
    threefry2x32(key.x, key.y, 0u, (uint32_t)i, o0, o1);
    uint32_t bits = o0 ^ o1;                       // partitionable 32-bit path
    float r = __uint_as_float((bits >> 9) | 0x3f800000u) - 1.0f;  // [0,1)
    float x = inp[i];
    float sp = 0.5f;                               // temp == 0 -> sp = 0.5
    if (r * 2.0f <= fabsf(x)) {
        if (x > 0.0f)      sp = 1.0f;
        else if (x < 0.0f) sp = 0.0f;
    }
    g_sp[i] = sp;
}

// ---------------- fused GEMM + LIF update per step --------------------------
// Z[b,j] = sp[b,:] . w1[j,:]  with Eigen kc=248 panel-blocked accumulation:
//   Z = ((fold[0,248) + fold[248,496)) + fold[496,744)) + fold[744,784)
// each fold = fresh accumulator, ascending-k FMA chain (Eigen gebp order).
// mem1 = 0.95*mem1 + 0.05*Z; spike if mem1-1>0; reset; count.
__global__ __launch_bounds__(256) void k_step(const float* __restrict__ w1) {
    __shared__ float As[8][128];
    __shared__ float Bs[8][128];

    const int tid = threadIdx.x;
    const int bx  = blockIdx.x;            // N tile (0..6)
    const int by  = blockIdx.y;            // M tile (0..63)
    const int tx  = tid & 15;
    const int ty  = tid >> 4;
    const int lr  = tid >> 1;              // load row within tile (0..127)
    const int lc  = (tid & 1) << 2;        // load col offset (0 or 4)

    const int rowA = by * 128 + lr;
    const int rowB = bx * 128 + lr;
    const bool bok = (rowB < N_DIM);

    const float* Aptr = g_sp + (size_t)rowA * K_DIM;
    const float* Bptr = w1   + (size_t)rowB * K_DIM;

    float csum[8][8];   // running C (panel sums added in order)
    float acc[8][8];    // current panel accumulator
    #pragma unroll
    for (int i = 0; i < 8; i++)
        #pragma unroll
        for (int j = 0; j < 8; j++) { csum[i][j] = 0.0f; acc[i][j] = 0.0f; }

    // Eigen kc=248 panel boundaries (multiples of the 8-wide k tile)
    const int pend[4] = {248, 496, 744, 784};
    int k0 = 0;
    #pragma unroll 1
    for (int p = 0; p < 4; p++) {
        #pragma unroll 1
        for (; k0 < pend[p]; k0 += 8) {
            float4 av = *(const float4*)(Aptr + k0 + lc);
            float4 bv = bok ? *(const float4*)(Bptr + k0 + lc)
                            : make_float4(0.f, 0.f, 0.f, 0.f);
            __syncthreads();
            As[lc + 0][lr] = av.x; As[lc + 1][lr] = av.y;
            As[lc + 2][lr] = av.z; As[lc + 3][lr] = av.w;
            Bs[lc + 0][lr] = bv.x; Bs[lc + 1][lr] = bv.y;
            Bs[lc + 2][lr] = bv.z; Bs[lc + 3][lr] = bv.w;
            __syncthreads();

            #pragma unroll
            for (int kk = 0; kk < 8; kk++) {
                float4 a0 = *(const float4*)&As[kk][ty * 8];
                float4 a1 = *(const float4*)&As[kk][ty * 8 + 4];
                float4 b0 = *(const float4*)&Bs[kk][tx * 8];
                float4 b1 = *(const float4*)&Bs[kk][tx * 8 + 4];
                float a[8] = {a0.x, a0.y, a0.z, a0.w, a1.x, a1.y, a1.z, a1.w};
                float b[8] = {b0.x, b0.y, b0.z, b0.w, b1.x, b1.y, b1.z, b1.w};
                #pragma unroll
                for (int i = 0; i < 8; i++)
                    #pragma unroll
                    for (int j = 0; j < 8; j++)
                        acc[i][j] = __fmaf_rn(a[i], b[j], acc[i][j]);
            }
        }
        // end of panel: C += s_panel (one rounded add), reset panel acc
        #pragma unroll
        for (int i = 0; i < 8; i++)
            #pragma unroll
            for (int j = 0; j < 8; j++) {
                csum[i][j] = __fadd_rn(csum[i][j], acc[i][j]);
                acc[i][j] = 0.0f;
            }
    }

    // epilogue: LIF update (non-contracted mul/mul/add, XLA elementwise order)
    const float cL = 0.95f;
    const float cI = 0.05000000074505806f;     // float32(1.0 - 0.95)
    const int mbase = by * 128 + ty * 8;
    const int nbase = bx * 128 + tx * 8;
    #pragma unroll
    for (int i = 0; i < 8; i++) {
        int b = mbase + i;
        #pragma unroll
        for (int j = 0; j < 8; j++) {
            int c = nbase + j;
            if (c < N_DIM) {
                size_t idx = (size_t)b * N_DIM + c;
                float m = g_mem1[idx];
                m = __fadd_rn(__fmul_rn(cL, m), __fmul_rn(cI, csum[i][j]));
                float thr = __fadd_rn(m, -1.0f);
                if (thr > 0.0f) { g_S[idx] += 1.0f; m = __fadd_rn(m, -1.0f); }
                g_mem1[idx] = m;
            }
        }
    }
}

// ---------------- final: out = (S @ w2^T) / 25 ------------------------------
// (no threshold downstream: ordering noise here is ~1e-7, far below 1e-3)
__global__ void k_final(const float* __restrict__ w2, float* __restrict__ out) {
    int gw   = (blockIdx.x * blockDim.x + threadIdx.x) >> 5;
    int lane = threadIdx.x & 31;
    if (gw >= B_ROWS * 10) return;
    int b = gw / 10, c = gw % 10;
    const float* srow = g_S + (size_t)b * N_DIM;
    const float* wrow = w2 + (size_t)c * N_DIM;
    float s = 0.0f;
    for (int k = lane; k < N_DIM; k += 32) s += srow[k] * wrow[k];
    #pragma unroll
    for (int off = 16; off; off >>= 1) s += __shfl_xor_sync(0xFFFFFFFFu, s, off);
    if (lane == 0) out[(size_t)b * 10 + c] = s / 25.0f;
}

// ---------------- launch ----------------------------------------------------
extern "C" void kernel_launch(void* const* d_in, const int* in_sizes, int n_in,
                              void* d_out, int out_size) {
    const float* inp = (const float*)d_in[0];   // [8192, 784]
    const float* w1  = (const float*)d_in[1];   // [800, 784]
    const float* w2  = (const float*)d_in[2];   // [10, 800]
    float* out = (float*)d_out;                 // [8192, 10]

    k_init<<<1, 32>>>();
    k_zero<<<(B_ROWS * N_DIM + 255) / 256, 256>>>();

    for (int t = 0; t < NSTEPS; t++) {
        k_spike<<<(B_ROWS * K_DIM + 255) / 256, 256>>>(inp, t);
        k_step<<<dim3(7, 64), 256>>>(w1);
    }

    k_final<<<(B_ROWS * 10 * 32 + 255) / 256, 256>>>(w2, out);
}

// round 5
// speedup vs baseline: 1.0074x; 1.0074x over previous
#include <cuda_runtime.h>
#include <cstdint>

#define B_ROWS 8192
#define K_DIM  784
#define N_DIM  800
#define NSTEPS 25

typedef unsigned long long ull;

// ---------------- device scratch (static globals: no runtime allocation) ----
__device__ float g_sp  [B_ROWS * K_DIM];   // Poisson spike matrix {0, 0.5, 1}
__device__ float g_mem1[B_ROWS * N_DIM];   // membrane potential
__device__ float g_S   [B_ROWS * N_DIM];   // spike counts
__device__ uint2 g_keys[NSTEPS];           // per-step threefry keys

// ---------------- packed f32x2 helpers (bit-exact per lane) -----------------
__device__ __forceinline__ ull pack2(float lo, float hi) {
    ull u; asm("mov.b64 %0, {%1, %2};" : "=l"(u) : "f"(lo), "f"(hi)); return u;
}
__device__ __forceinline__ void unpack2(ull u, float &lo, float &hi) {
    asm("mov.b64 {%0, %1}, %2;" : "=f"(lo), "=f"(hi) : "l"(u));
}
__device__ __forceinline__ ull fma2(ull a, ull b, ull c) {
    ull d; asm("fma.rn.f32x2 %0, %1, %2, %3;" : "=l"(d) : "l"(a), "l"(b), "l"(c));
    return d;
}
__device__ __forceinline__ ull add2(ull a, ull b) {
    ull d; asm("add.rn.f32x2 %0, %1, %2;" : "=l"(d) : "l"(a), "l"(b));
    return d;
}

// ---------------- threefry2x32 (matches JAX, 20 rounds) --------------------
__device__ __forceinline__ void threefry2x32(uint32_t k0, uint32_t k1,
                                             uint32_t x0, uint32_t x1,
                                             uint32_t &o0, uint32_t &o1) {
    uint32_t ks0 = k0, ks1 = k1, ks2 = 0x1BD11BDAu ^ k0 ^ k1;
    x0 += ks0; x1 += ks1;
#define TF_R(r) { x0 += x1; x1 = __funnelshift_l(x1, x1, (r)); x1 ^= x0; }
    TF_R(13) TF_R(15) TF_R(26) TF_R(6)
    x0 += ks1; x1 += ks2 + 1u;
    TF_R(17) TF_R(29) TF_R(16) TF_R(24)
    x0 += ks2; x1 += ks0 + 2u;
    TF_R(13) TF_R(15) TF_R(26) TF_R(6)
    x0 += ks0; x1 += ks1 + 3u;
    TF_R(17) TF_R(29) TF_R(16) TF_R(24)
    x0 += ks1; x1 += ks2 + 4u;
    TF_R(13) TF_R(15) TF_R(26) TF_R(6)
    x0 += ks2; x1 += ks0 + 5u;
#undef TF_R
    o0 = x0; o1 = x1;
}

// ---------------- init: per-step keys ---------------------------------------
__global__ void k_init() {
    int t = threadIdx.x;
    if (t < NSTEPS) {
        uint32_t o0, o1;
        threefry2x32(0u, 42u, 0u, (uint32_t)t, o0, o1);
        g_keys[t] = make_uint2(o0, o1);
    }
}

// ---------------- zero state ------------------------------------------------
__global__ void k_zero() {
    int i = blockIdx.x * blockDim.x + threadIdx.x;
    if (i < B_ROWS * N_DIM) { g_mem1[i] = 0.0f; g_S[i] = 0.0f; }
}

// ---------------- per-step spike (Poisson) generation -----------------------
__global__ void k_spike(const float* __restrict__ inp, int t) {
    int i = blockIdx.x * blockDim.x + threadIdx.x;
    if (i >= B_ROWS * K_DIM) return;
    uint2 key = g_keys[t];
    uint32_t o0, o1;
    threefry2x32(key.x, key.y, 0u, (uint32_t)i, o0, o1);
    uint32_t bits = o0 ^ o1;
    float r = __uint_as_float((bits >> 9) | 0x3f800000u) - 1.0f;  // [0,1)
    float x = inp[i];
    float sp = 0.5f;
    if (r * 2.0f <= fabsf(x)) {
        if (x > 0.0f)      sp = 1.0f;
        else if (x < 0.0f) sp = 0.0f;
    }
    g_sp[i] = sp;
}

// ---------------- fused GEMM + LIF update per step --------------------------
// Z[b,j] = sp[b,:] . w1[j,:]   Eigen kc=248 panel folds at 248/496/744/784.
// f32x2 packs (j, j+1) pairs; per-lane chains identical to scalar version.
#define NTILES (K_DIM / 8)   // 98
__global__ __launch_bounds__(256) void k_step(const float* __restrict__ w1) {
    __shared__ float As[2][8][128];
    __shared__ float Bs[2][8][128];

    const int tid = threadIdx.x;
    const int bx  = blockIdx.x;            // N tile (0..6)
    const int by  = blockIdx.y;            // M tile (0..63)
    const int tx  = tid & 15;
    const int ty  = tid >> 4;
    const int lr  = tid >> 1;              // load row within tile (0..127)
    const int lc  = (tid & 1) << 2;        // load col offset (0 or 4)

    const int rowA = by * 128 + lr;
    const int rowB = bx * 128 + lr;
    const bool bok = (rowB < N_DIM);

    const float* Aptr = g_sp + (size_t)rowA * K_DIM;
    const float* Bptr = w1   + (size_t)rowB * K_DIM;

    ull csum[8][4];   // C pairs: [row i][pair q] = (C[i][2q], C[i][2q+1])
    ull acc [8][4];   // current panel accumulator pairs
    const ull z2 = 0ull;
    #pragma unroll
    for (int i = 0; i < 8; i++)
        #pragma unroll
        for (int q = 0; q < 4; q++) { csum[i][q] = z2; acc[i][q] = z2; }

    // prologue: load + store tile 0
    float4 av = *(const float4*)(Aptr + lc);
    float4 bv = bok ? *(const float4*)(Bptr + lc)
                    : make_float4(0.f, 0.f, 0.f, 0.f);
    As[0][lc + 0][lr] = av.x; As[0][lc + 1][lr] = av.y;
    As[0][lc + 2][lr] = av.z; As[0][lc + 3][lr] = av.w;
    Bs[0][lc + 0][lr] = bv.x; Bs[0][lc + 1][lr] = bv.y;
    Bs[0][lc + 2][lr] = bv.z; Bs[0][lc + 3][lr] = bv.w;
    __syncthreads();

    int next_fold = 248;
    #pragma unroll 1
    for (int t = 0; t < NTILES; t++) {
        const int cur = t & 1;
        // prefetch tile t+1 into registers (LDG latency hidden by FMA block)
        if (t + 1 < NTILES) {
            const int k1 = (t + 1) * 8;
            av = *(const float4*)(Aptr + k1 + lc);
            bv = bok ? *(const float4*)(Bptr + k1 + lc)
                     : make_float4(0.f, 0.f, 0.f, 0.f);
        }

        // compute on tile t
        #pragma unroll
        for (int kk = 0; kk < 8; kk++) {
            float4 b0 = *(const float4*)&Bs[cur][kk][tx * 8];
            float4 b1 = *(const float4*)&Bs[cur][kk][tx * 8 + 4];
            float4 a0 = *(const float4*)&As[cur][kk][ty * 8];
            float4 a1 = *(const float4*)&As[cur][kk][ty * 8 + 4];
            ull bp[4] = { pack2(b0.x, b0.y), pack2(b0.z, b0.w),
                          pack2(b1.x, b1.y), pack2(b1.z, b1.w) };
            float a[8] = {a0.x, a0.y, a0.z, a0.w, a1.x, a1.y, a1.z, a1.w};
            #pragma unroll
            for (int i = 0; i < 8; i++) {
                ull ad = pack2(a[i], a[i]);
                #pragma unroll
                for (int q = 0; q < 4; q++)
                    acc[i][q] = fma2(ad, bp[q], acc[i][q]);
            }
        }

        // store tile t+1 into the other buffer, one barrier per tile
        if (t + 1 < NTILES) {
            const int nxt = cur ^ 1;
            As[nxt][lc + 0][lr] = av.x; As[nxt][lc + 1][lr] = av.y;
            As[nxt][lc + 2][lr] = av.z; As[nxt][lc + 3][lr] = av.w;
            Bs[nxt][lc + 0][lr] = bv.x; Bs[nxt][lc + 1][lr] = bv.y;
            Bs[nxt][lc + 2][lr] = bv.z; Bs[nxt][lc + 3][lr] = bv.w;
            __syncthreads();
        }

        // Eigen panel fold boundaries: k = 248, 496, 744, 784
        const int kend = (t + 1) * 8;
        if (kend == next_fold || kend == K_DIM) {
            #pragma unroll
            for (int i = 0; i < 8; i++)
                #pragma unroll
                for (int q = 0; q < 4; q++) {
                    csum[i][q] = add2(csum[i][q], acc[i][q]);
                    acc[i][q] = z2;
                }
            next_fold += 248;
        }
    }

    // epilogue: LIF update (non-contracted, matches XLA elementwise order)
    const float cL = 0.95f;
    const float cI = 0.05000000074505806f;     // float32(1.0 - 0.95)
    const int mbase = by * 128 + ty * 8;
    const int nbase = bx * 128 + tx * 8;
    #pragma unroll
    for (int i = 0; i < 8; i++) {
        int b = mbase + i;
        #pragma unroll
        for (int q = 0; q < 4; q++) {
            float zlo, zhi;
            unpack2(csum[i][q], zlo, zhi);
            float zz[2] = {zlo, zhi};
            #pragma unroll
            for (int h = 0; h < 2; h++) {
                int c = nbase + 2 * q + h;
                if (c < N_DIM) {
                    size_t idx = (size_t)b * N_DIM + c;
                    float m = g_mem1[idx];
                    m = __fadd_rn(__fmul_rn(cL, m), __fmul_rn(cI, zz[h]));
                    float thr = __fadd_rn(m, -1.0f);
                    if (thr > 0.0f) { g_S[idx] += 1.0f; m = __fadd_rn(m, -1.0f); }
                    g_mem1[idx] = m;
                }
            }
        }
    }
}

// ---------------- final: out = (S @ w2^T) / 25 ------------------------------
__global__ void k_final(const float* __restrict__ w2, float* __restrict__ out) {
    int gw   = (blockIdx.x * blockDim.x + threadIdx.x) >> 5;
    int lane = threadIdx.x & 31;
    if (gw >= B_ROWS * 10) return;
    int b = gw / 10, c = gw % 10;
    const float* srow = g_S + (size_t)b * N_DIM;
    const float* wrow = w2 + (size_t)c * N_DIM;
    float s = 0.0f;
    for (int k = lane; k < N_DIM; k += 32) s += srow[k] * wrow[k];
    #pragma unroll
    for (int off = 16; off; off >>= 1) s += __shfl_xor_sync(0xFFFFFFFFu, s, off);
    if (lane == 0) out[(size_t)b * 10 + c] = s / 25.0f;
}

// ---------------- launch ----------------------------------------------------
extern "C" void kernel_launch(void* const* d_in, const int* in_sizes, int n_in,
                              void* d_out, int out_size) {
    const float* inp = (const float*)d_in[0];   // [8192, 784]
    const float* w1  = (const float*)d_in[1];   // [800, 784]
    const float* w2  = (const float*)d_in[2];   // [10, 800]
    float* out = (float*)d_out;                 // [8192, 10]

    k_init<<<1, 32>>>();
    k_zero<<<(B_ROWS * N_DIM + 255) / 256, 256>>>();

    for (int t = 0; t < NSTEPS; t++) {
        k_spike<<<(B_ROWS * K_DIM + 255) / 256, 256>>>(inp, t);
        k_step<<<dim3(7, 64), 256>>>(w1);
    }

    k_final<<<(B_ROWS * 10 * 32 + 255) / 256, 256>>>(w2, out);
}